// round 6
// baseline (speedup 1.0000x reference)
#include <cuda_runtime.h>
#include <cuda_fp16.h>
#include <math.h>
#include <stdint.h>

#define BB 16
#define NN 2048
#define CC 128

// ---------------- device scratch ----------------
__device__ __half g_WsymH[CC * CC];          // 32 KB fp16
__device__ __half g_Hh[BB * NN * CC];        // 8 MB fp16
__device__ float  g_bias[(size_t)NN * NN];   // 16 MB combined mask+diag+A_stat

// ---------------- helpers ----------------
__device__ __forceinline__ uint32_t smem_u32(const void* p) {
    uint32_t a;
    asm("{ .reg .u64 t; cvta.to.shared.u64 t, %1; cvt.u32.u64 %0, t; }" : "=r"(a) : "l"(p));
    return a;
}
__device__ __forceinline__ void cpasync16(uint32_t s, const void* g) {
    asm volatile("cp.async.cg.shared.global [%0], [%1], 16;" :: "r"(s), "l"(g));
}
#define CP_COMMIT() asm volatile("cp.async.commit_group;" ::: "memory")
#define CP_WAIT1()  asm volatile("cp.async.wait_group 1;" ::: "memory")

#define LDSM_X4(r0, r1, r2, r3, addr) \
    asm volatile("ldmatrix.sync.aligned.m8n8.x4.shared.b16 {%0,%1,%2,%3}, [%4];" \
        : "=r"(r0), "=r"(r1), "=r"(r2), "=r"(r3) : "r"(addr))

#define MMA16816(d, a, b0, b1) \
    asm volatile("mma.sync.aligned.m16n8k16.row.col.f32.f16.f16.f32 " \
        "{%0,%1,%2,%3}, {%4,%5,%6,%7}, {%8,%9}, {%0,%1,%2,%3};" \
        : "+f"((d)[0]), "+f"((d)[1]), "+f"((d)[2]), "+f"((d)[3]) \
        : "r"((a)[0]), "r"((a)[1]), "r"((a)[2]), "r"((a)[3]), "r"(b0), "r"(b1))

// ---------------- W_sym ----------------
__global__ void k_wsym(const float* __restrict__ Wq, const float* __restrict__ Wk) {
    int k = blockIdx.x, c = threadIdx.x;
    float a1 = 0.f, a2 = 0.f;
    for (int e = 0; e < CC; e++) {
        a1 += Wq[e * CC + k] * Wk[e * CC + c];
        a2 += Wk[e * CC + k] * Wq[e * CC + c];
    }
    g_WsymH[k * CC + c] = __float2half((0.5f / (sqrtf(128.0f) * 1.5f)) * (a1 + a2));
}

// ---------------- H -> fp16 ----------------
__global__ void k_splitH(const float* __restrict__ H) {
    size_t i = ((size_t)blockIdx.x * blockDim.x + threadIdx.x) * 4;
    float4 v = *(const float4*)(H + i);
    __half2* dst = (__half2*)(g_Hh + i);
    dst[0] = __floats2half2_rn(v.x, v.y);
    dst[1] = __floats2half2_rn(v.z, v.w);
}

// ---------------- combined bias ----------------
__global__ void k_bias(const float* __restrict__ Ast, const float* __restrict__ Mm) {
    size_t idx4 = (size_t)blockIdx.x * blockDim.x + threadIdx.x;
    int n = (int)(idx4 >> 9);
    int mb = (int)(idx4 & 511) * 4;
    float4 a = ((const float4*)Ast)[idx4];
    float4 m = ((const float4*)Mm)[idx4];
    float4 o;
    o.x = (m.x <= 0.f || mb + 0 == n) ? -1e30f : a.x;
    o.y = (m.y <= 0.f || mb + 1 == n) ? -1e30f : a.y;
    o.z = (m.z <= 0.f || mb + 2 == n) ? -1e30f : a.z;
    o.w = (m.w <= 0.f || mb + 3 == n) ? -1e30f : a.w;
    ((float4*)g_bias)[idx4] = o;
}

// ---------------- persistent main, two-pass recompute ----------------
// CTA = (rt, b). smem: bufA 32K | bufB0 32K | bufB1 32K | rowsum 2K | invs 512B
// Phase 1: G = H_rt @ Wsym -> bufA.
// t = 0..15  : GEMM + exp sums only (no stores)
// t = 16..31 : GEMM recompute + exp * inv -> single normalized store
__global__ void __launch_bounds__(256, 2) k_main(float* __restrict__ out) {
    extern __shared__ char smem[];
    uint32_t sm = smem_u32(smem);
    float* rowsum = (float*)(smem + 98304);   // [128][4]
    float* invs   = (float*)(smem + 98304 + 2048);
    int tid = threadIdx.x, wid = tid >> 5, lane = tid & 31;
    int rt = blockIdx.x, b = blockIdx.y;

    ((float2*)rowsum)[tid] = make_float2(0.f, 0.f);

    const __half* Hrt = g_Hh + ((size_t)(b * NN + rt * 128)) * CC;

    // group1: H_rt -> bufA, Wsym -> bufB0
    #pragma unroll
    for (int it = 0; it < 8; it++) {
        int idx = it * 256 + tid;
        int m = idx >> 4, c = idx & 15;
        uint32_t dst = (uint32_t)(m * 256 + ((c ^ (m & 7)) << 4));
        cpasync16(sm + dst, Hrt + (size_t)idx * 8);
        cpasync16(sm + 32768 + dst, g_WsymH + idx * 8);
    }
    CP_COMMIT();
    // group2: ct=0 -> bufB1
    {
        const __half* Bp = g_Hh + (size_t)(b * NN) * CC;
        #pragma unroll
        for (int it = 0; it < 8; it++) {
            int idx = it * 256 + tid;
            int m = idx >> 4, c = idx & 15;
            uint32_t dst = (uint32_t)(m * 256 + ((c ^ (m & 7)) << 4));
            cpasync16(sm + 65536 + dst, Bp + (size_t)idx * 8);
        }
    }
    CP_COMMIT();

    int wm = wid >> 2, wn = wid & 3;          // warp tile 64(m) x 32(n)
    int mo = wm * 64, no = wn * 32;
    int lr = lane & 15, cb = lane >> 4, l7 = lane & 7;
    int q = lane >> 2, qq = (lane & 3) * 2;

    uint32_t rowAoff[4], rowBoff[2];
    #pragma unroll
    for (int i = 0; i < 4; i++) rowAoff[i] = (uint32_t)(mo + i * 16 + lr) * 256u;
    #pragma unroll
    for (int j = 0; j < 2; j++) rowBoff[j] = (uint32_t)(no + j * 16 + lr) * 256u;

    float acc[4][4][4];

    // ---- Phase 1: G tile ----
    CP_WAIT1();
    __syncthreads();
    #pragma unroll
    for (int i = 0; i < 4; i++)
        #pragma unroll
        for (int j = 0; j < 4; j++)
            #pragma unroll
            for (int p = 0; p < 4; p++) acc[i][j][p] = 0.f;
    #pragma unroll
    for (int ks = 0; ks < 8; ks++) {
        uint32_t sw = (uint32_t)(((2 * ks + cb) ^ l7) << 4);
        uint32_t a[4][4], bf[2][4];
        #pragma unroll
        for (int i = 0; i < 4; i++)
            LDSM_X4(a[i][0], a[i][1], a[i][2], a[i][3], sm + rowAoff[i] + sw);
        #pragma unroll
        for (int j = 0; j < 2; j++)
            LDSM_X4(bf[j][0], bf[j][1], bf[j][2], bf[j][3], sm + 32768u + rowBoff[j] + sw);
        #pragma unroll
        for (int i = 0; i < 4; i++)
            #pragma unroll
            for (int j = 0; j < 4; j++)
                MMA16816(acc[i][j], a[i], bf[j >> 1][j & 1], bf[j >> 1][2 + (j & 1)]);
    }
    __syncthreads();

    // store G fragments into bufA (fp16, swizzled A layout)
    #pragma unroll
    for (int i = 0; i < 4; i++) {
        int r1 = mo + i * 16 + q;
        #pragma unroll
        for (int j = 0; j < 4; j++) {
            int c = no + j * 8 + qq;
            uint32_t ch = (uint32_t)(c >> 3);
            uint32_t off1 = (uint32_t)r1 * 256u + ((ch ^ ((uint32_t)r1 & 7)) << 4) + (uint32_t)(c & 7) * 2u;
            int r2 = r1 + 8;
            uint32_t off2 = (uint32_t)r2 * 256u + ((ch ^ ((uint32_t)r2 & 7)) << 4) + (uint32_t)(c & 7) * 2u;
            *(__half2*)(smem + off1) = __floats2half2_rn(acc[i][j][0], acc[i][j][1]);
            *(__half2*)(smem + off2) = __floats2half2_rn(acc[i][j][2], acc[i][j][3]);
        }
    }
    // group3: ct=1 -> bufB0
    {
        const __half* Bp = g_Hh + ((size_t)(b * NN + 128)) * CC;
        #pragma unroll
        for (int it = 0; it < 8; it++) {
            int idx = it * 256 + tid;
            int m = idx >> 4, c = idx & 15;
            uint32_t dst = (uint32_t)(m * 256 + ((c ^ (m & 7)) << 4));
            cpasync16(sm + 32768 + dst, Bp + (size_t)idx * 8);
        }
    }
    CP_COMMIT();
    __syncthreads();   // G stores visible

    // ---- unified 32-iteration loop: t<16 sum pass, t>=16 write pass ----
    size_t obase = (size_t)b * NN * NN;

    #pragma unroll 1
    for (int t = 0; t < 32; t++) {
        int ct = t & 15;
        uint32_t Bb = sm + 32768u + (uint32_t)(((t & 1) ^ 1) << 15);
        CP_WAIT1();
        __syncthreads();

        #pragma unroll
        for (int i = 0; i < 4; i++)
            #pragma unroll
            for (int j = 0; j < 4; j++)
                #pragma unroll
                for (int p = 0; p < 4; p++) acc[i][j][p] = 0.f;
        #pragma unroll
        for (int ks = 0; ks < 8; ks++) {
            uint32_t sw = (uint32_t)(((2 * ks + cb) ^ l7) << 4);
            uint32_t a[4][4], bf[2][4];
            #pragma unroll
            for (int i = 0; i < 4; i++)
                LDSM_X4(a[i][0], a[i][1], a[i][2], a[i][3], sm + rowAoff[i] + sw);
            #pragma unroll
            for (int j = 0; j < 2; j++)
                LDSM_X4(bf[j][0], bf[j][1], bf[j][2], bf[j][3], Bb + rowBoff[j] + sw);
            #pragma unroll
            for (int i = 0; i < 4; i++)
                #pragma unroll
                for (int j = 0; j < 4; j++)
                    MMA16816(acc[i][j], a[i], bf[j >> 1][j & 1], bf[j >> 1][2 + (j & 1)]);
        }
        __syncthreads();   // done reading this B slot

        // prefetch the tile needed at t+2 into the freed slot
        if (t + 2 < 32) {
            int c2 = (t + 2) & 15;
            const __half* Bp = g_Hh + ((size_t)(b * NN + c2 * 128)) * CC;
            #pragma unroll
            for (int it = 0; it < 8; it++) {
                int idx = it * 256 + tid;
                int m = idx >> 4, c = idx & 15;
                uint32_t dst = (uint32_t)(m * 256 + ((c ^ (m & 7)) << 4));
                cpasync16(Bb + dst, Bp + (size_t)idx * 8);
            }
        }
        CP_COMMIT();

        // pass boundary: compute 1/rowsum once
        if (t == 16) {
            if (tid < 128) {
                float s = rowsum[tid * 4] + rowsum[tid * 4 + 1]
                        + rowsum[tid * 4 + 2] + rowsum[tid * 4 + 3];
                invs[tid] = 1.0f / s;
            }
            __syncthreads();
        }

        int gc0 = ct * 128 + no;
        if (t < 16) {
            // ---- sum pass: exp + rowsum, no stores ----
            #pragma unroll
            for (int i = 0; i < 4; i++) {
                int lrow = mo + i * 16 + q;
                int r1 = rt * 128 + lrow, r2 = r1 + 8;
                const float* b1p = g_bias + (size_t)r1 * NN;
                const float* b2p = g_bias + (size_t)r2 * NN;
                float s1 = 0.f, s2 = 0.f;
                #pragma unroll
                for (int j = 0; j < 4; j++) {
                    int c = gc0 + j * 8 + qq;
                    float2 bb1 = *(const float2*)(b1p + c);
                    float2 bb2 = *(const float2*)(b2p + c);
                    s1 += __expf(acc[i][j][0] + bb1.x) + __expf(acc[i][j][1] + bb1.y);
                    s2 += __expf(acc[i][j][2] + bb2.x) + __expf(acc[i][j][3] + bb2.y);
                }
                #pragma unroll
                for (int o = 1; o < 4; o <<= 1) {
                    s1 += __shfl_xor_sync(0xffffffffu, s1, o);
                    s2 += __shfl_xor_sync(0xffffffffu, s2, o);
                }
                if ((lane & 3) == 0) {
                    rowsum[lrow * 4 + wn] += s1;
                    rowsum[(lrow + 8) * 4 + wn] += s2;
                }
            }
        } else {
            // ---- write pass: exp * inv -> normalized store ----
            #pragma unroll
            for (int i = 0; i < 4; i++) {
                int lrow = mo + i * 16 + q;
                int r1 = rt * 128 + lrow, r2 = r1 + 8;
                float inv1 = invs[lrow], inv2 = invs[lrow + 8];
                const float* b1p = g_bias + (size_t)r1 * NN;
                const float* b2p = g_bias + (size_t)r2 * NN;
                #pragma unroll
                for (int j = 0; j < 4; j++) {
                    int c = gc0 + j * 8 + qq;
                    float2 bb1 = *(const float2*)(b1p + c);
                    float2 bb2 = *(const float2*)(b2p + c);
                    float2 e1, e2;
                    e1.x = __expf(acc[i][j][0] + bb1.x) * inv1;
                    e1.y = __expf(acc[i][j][1] + bb1.y) * inv1;
                    e2.x = __expf(acc[i][j][2] + bb2.x) * inv2;
                    e2.y = __expf(acc[i][j][3] + bb2.y) * inv2;
                    *(float2*)(out + obase + (size_t)r1 * NN + c) = e1;
                    *(float2*)(out + obase + (size_t)r2 * NN + c) = e2;
                }
            }
        }
    }
}

// ---------------- launch ----------------
extern "C" void kernel_launch(void* const* d_in, const int* in_sizes, int n_in,
                              void* d_out, int out_size) {
    const float* H   = (const float*)d_in[0];
    const float* Ast = (const float*)d_in[1];
    const float* Mm  = (const float*)d_in[2];
    const float* Wq  = (const float*)d_in[3];
    const float* Wk  = (const float*)d_in[4];
    float* out = (float*)d_out;

    static bool attr_done = false;
    if (!attr_done) {
        cudaFuncSetAttribute(k_main, cudaFuncAttributeMaxDynamicSharedMemorySize, 101376);
        attr_done = true;
    }

    k_wsym<<<CC, CC>>>(Wq, Wk);
    k_splitH<<<(BB * NN * CC / 4) / 256, 256>>>(H);
    k_bias<<<((size_t)NN * NN / 4) / 256, 256>>>(Ast, Mm);
    {
        dim3 grid(NN / 128, BB);   // (rt, b)
        k_main<<<grid, 256, 101376>>>(out);
    }
}